// round 12
// baseline (speedup 1.0000x reference)
#include <cuda_runtime.h>
#include <math.h>

typedef unsigned long long ull;
typedef long long ll;

#define NMAX 10000
#define EMAX 100000

__device__ __align__(16) float g_qt[NMAX * 20];  // per-node pre-rotated query
__device__ float g_z[NMAX];                      // softmax denominators
__device__ float g_ex[EMAX];                     // per-edge exp(dot)
__device__ __align__(16) float g_vv[EMAX * 40];  // per-edge value irreps
__device__ int g_is64;                           // edge_index dtype flag

#define INV_SQRT3  0.5773502691896258f
#define INV_SQRT2  0.7071067811865476f
#define INV_SQRT8  0.35355339059327373f
#define INV_SQRT24 0.2041241452319315f
#define INV_SQRT32 0.17677669529663687f
#define INV_SQRT80 0.11180339887498948f

__device__ __forceinline__ ll eidx(const void* ei, int pos) {
    if (g_is64) return ((const ll*)ei)[pos];
    return (ll)((const int*)ei)[pos];
}

// ---------------- packed f32x2 helpers ----------------
__device__ __forceinline__ ull pack2(float a, float b) {
    ull r; asm("mov.b64 %0, {%1,%2};" : "=l"(r) : "f"(a), "f"(b)); return r;
}
__device__ __forceinline__ void fma2(ull& acc, ull w, ull h) {
    asm("fma.rn.f32x2 %0, %1, %2, %0;" : "+l"(acc) : "l"(w), "l"(h));
}
__device__ __forceinline__ ull add2(ull a, ull b) {
    ull r; asm("add.rn.f32x2 %0, %1, %2;" : "=l"(r) : "l"(a), "l"(b)); return r;
}
__device__ __forceinline__ float2 unpack2(ull v) {
    float2 r; asm("mov.b64 {%0,%1}, %2;" : "=f"(r.x), "=f"(r.y) : "l"(v)); return r;
}
__device__ __forceinline__ float hsum2(ull v) {
    float2 a = unpack2(v); return a.x + a.y;
}
__device__ __forceinline__ float comb(float v) {
    return v + __shfl_xor_sync(0xffffffffu, v, 1);
}

// 2-edge group chunk: this lane's h-half partial weights for outputs j=2g,2g+1,
// consumed for two edges' hidden halves h0, h1.
__device__ __forceinline__ void gch(const float* __restrict__ Wb,
                                    const ull* h0, const ull* h1,
                                    ull& w00, ull& w10, ull& w01, ull& w11) {
    ull a0 = 0, b0 = 0, a1 = 0, b1 = 0;
#pragma unroll
    for (int k = 0; k < 8; k++) {
        const ulonglong2 c = *reinterpret_cast<const ulonglong2*>(Wb + k * 8);
        fma2(a0, c.x, h0[k]); fma2(b0, c.y, h0[k]);
        fma2(a1, c.x, h1[k]); fma2(b1, c.y, h1[k]);
    }
    w00 = a0; w10 = b0; w01 = a1; w11 = b1;
}

// single-edge group chunk
__device__ __forceinline__ void gch1(const float* __restrict__ Wb, const ull* h,
                                     ull& w0, ull& w1) {
    ull a0 = 0, b0 = 0, a1 = 0, b1 = 0;
#pragma unroll
    for (int k = 0; k < 8; k += 2) {
        const ulonglong2 c0 = *reinterpret_cast<const ulonglong2*>(Wb + k * 8);
        const ulonglong2 c1 = *reinterpret_cast<const ulonglong2*>(Wb + k * 8 + 8);
        fma2(a0, c0.x, h[k]);     fma2(b0, c0.y, h[k]);
        fma2(a1, c1.x, h[k + 1]); fma2(b1, c1.y, h[k + 1]);
    }
    w0 = add2(a0, a1); w1 = add2(b0, b1);
}

// hidden half: this lane computes cols [par*16, par*16+16), hh[k] = {col 2k, col 2k+1}
__device__ __forceinline__ void compute_h16p(const float* __restrict__ W1,
                                             const float* es, ull* hh, int par) {
    ull acc2[8];
#pragma unroll
    for (int x = 0; x < 8; x++) acc2[x] = 0;
    const float* base = W1 + par * 16;
#pragma unroll
    for (int i = 0; i < 16; i++) {
        const ull ep = pack2(es[i], es[i]);
#pragma unroll
        for (int xl = 0; xl < 8; xl += 2) {
            const ulonglong2 w = *reinterpret_cast<const ulonglong2*>(base + i * 32 + xl * 2);
            fma2(acc2[xl], w.x, ep);
            fma2(acc2[xl + 1], w.y, ep);
        }
    }
#pragma unroll
    for (int x = 0; x < 8; x++) {
        float2 a = unpack2(acc2[x]);
        float t0 = a.x * 0.25f, t1 = a.y * 0.25f;
        float s0 = t0 / (1.f + __expf(-t0)) * INV_SQRT32;
        float s1 = t1 / (1.f + __expf(-t1)) * INV_SQRT32;
        hh[x] = pack2(s0, s1);
    }
}

__device__ __forceinline__ void load_es(float* es, const float* __restrict__ edge_scalars, int e) {
    const float4* p = (const float4*)(edge_scalars + (size_t)e * 16);
#pragma unroll
    for (int t = 0; t < 4; t++) {
        float4 v = p[t];
        es[t * 4 + 0] = v.x; es[t * 4 + 1] = v.y; es[t * 4 + 2] = v.z; es[t * 4 + 3] = v.w;
    }
}

// path2 coefficients (xv . shv)/sqrt3
__device__ __forceinline__ void compute_c2(const float* __restrict__ nf, float4 sq, float* c2) {
    float xv[24];
    const float4* q = (const float4*)(nf + 16);
#pragma unroll
    for (int t = 0; t < 6; t++) {
        float4 v = q[t];
        xv[t * 4 + 0] = v.x; xv[t * 4 + 1] = v.y; xv[t * 4 + 2] = v.z; xv[t * 4 + 3] = v.w;
    }
#pragma unroll
    for (int i = 0; i < 8; i++)
        c2[i] = (xv[i * 3] * sq.y + xv[i * 3 + 1] * sq.z + xv[i * 3 + 2] * sq.w) * INV_SQRT3;
}

// pair-pack a W2 slice into smem: float4 idx = (g*8+k)*2+par,
// value = {W[h0][C0+2g], W[h0+1][C0+2g], W[h0][C0+2g+1], W[h0+1][C0+2g+1]}, h0 = par*16+2k.
template <int NG, int S, int C0>
__device__ __forceinline__ void pack_w2(float4* pk, const float* __restrict__ w2, int tid) {
    for (int idx = tid; idx < NG * 16; idx += 128) {
        const int p = idx & 1, t = idx >> 1, k = t & 7, g = t >> 3;
        const float* r0 = w2 + (p * 16 + 2 * k) * S + C0 + 2 * g;
        float2 a = *(const float2*)r0;
        float2 b = *(const float2*)(r0 + S);
        pk[idx] = make_float4(a.x, b.x, a.y, b.y);
    }
}

// ---------------- tiny kernels ----------------
__global__ void k_detect(const int* __restrict__ ei32, int twoE) {
    __shared__ int any;
    if (threadIdx.x == 0) any = 0;
    __syncthreads();
    int nchk = (twoE < 2048 ? twoE : 2048);
    for (int i = threadIdx.x; i < nchk / 2; i += blockDim.x)
        if (ei32[2 * i + 1] != 0) any = 1;
    __syncthreads();
    if (threadIdx.x == 0) g_is64 = (any == 0);
}

__global__ void k_zero(float* __restrict__ out, int N) {
    int i = blockIdx.x * blockDim.x + threadIdx.x;
    if (i < N * 40) out[i] = 0.f;
    if (i < N) g_z[i] = 0.f;
}

__global__ void k_query(const float* __restrict__ node_ft, const float* __restrict__ wqs,
                        const float* __restrict__ wqv, const float* __restrict__ wds,
                        const float* __restrict__ wdv, int N) {
    int n = blockIdx.x * blockDim.x + threadIdx.x;
    if (n >= N) return;
    const float* x = node_ft + (size_t)n * 40;
    float xs[16], xv[24];
#pragma unroll
    for (int i = 0; i < 16; i++) xs[i] = x[i];
#pragma unroll
    for (int i = 0; i < 24; i++) xv[i] = x[16 + i];

    float qs[8];
#pragma unroll
    for (int o = 0; o < 8; o++) qs[o] = 0.f;
#pragma unroll
    for (int i = 0; i < 16; i++) {
        const float c = xs[i];
#pragma unroll
        for (int o = 0; o < 8; o++) qs[o] += c * __ldg(wqs + i * 8 + o);
    }
#pragma unroll
    for (int o = 0; o < 8; o++) qs[o] *= 0.25f;

    float qv[12];
#pragma unroll
    for (int o = 0; o < 12; o++) qv[o] = 0.f;
#pragma unroll
    for (int i = 0; i < 8; i++) {
#pragma unroll
        for (int o = 0; o < 4; o++) {
            const float w = __ldg(wqv + i * 4 + o);
            qv[o * 3 + 0] += xv[i * 3 + 0] * w;
            qv[o * 3 + 1] += xv[i * 3 + 1] * w;
            qv[o * 3 + 2] += xv[i * 3 + 2] * w;
        }
    }
#pragma unroll
    for (int o = 0; o < 12; o++) qv[o] *= INV_SQRT8;

    float qt[20];
#pragma unroll
    for (int o = 0; o < 20; o++) qt[o] = 0.f;
#pragma unroll
    for (int i = 0; i < 8; i++) {
        const float c = qs[i];
#pragma unroll
        for (int o = 0; o < 8; o++) qt[o] += c * __ldg(wds + i * 8 + o);
    }
#pragma unroll
    for (int i = 0; i < 4; i++) {
#pragma unroll
        for (int o = 0; o < 4; o++) {
            const float w = __ldg(wdv + i * 4 + o);
            qt[8 + o * 3 + 0] += qv[i * 3 + 0] * w;
            qt[8 + o * 3 + 1] += qv[i * 3 + 1] * w;
            qt[8 + o * 3 + 2] += qv[i * 3 + 2] * w;
        }
    }
    float* dst = g_qt + (size_t)n * 20;
#pragma unroll
    for (int t = 0; t < 20; t++) dst[t] = qt[t];
}

// K paths 4+5 for one edge (outputs o<4, all vector comps)
__device__ __forceinline__ void k45(const float* __restrict__ W, const float* __restrict__ nfm,
                                    const float4 sqm, const ull* hhm, float* kvm) {
    float xv[24];
    const float4* q = (const float4*)(nfm + 16);
#pragma unroll
    for (int t = 0; t < 6; t++) {
        float4 v = q[t];
        xv[t * 4 + 0] = v.x; xv[t * 4 + 1] = v.y; xv[t * 4 + 2] = v.z; xv[t * 4 + 3] = v.w;
    }
#pragma unroll
    for (int i = 0; i < 8; i++) {
        const float a0 = xv[i * 3], a1 = xv[i * 3 + 1], a2 = xv[i * 3 + 2];
        {
            const float p0 = a0 * sqm.x, p1 = a1 * sqm.x, p2 = a2 * sqm.x;
#pragma unroll
            for (int og = 0; og < 2; og++) {
                ull w0, w1;
                gch1(W + (128 + i * 2 + og) * 64, hhm, w0, w1);
                const float f0 = hsum2(w0), f1 = hsum2(w1);
                kvm[(2 * og) * 3 + 0] += p0 * f0; kvm[(2 * og) * 3 + 1] += p1 * f0; kvm[(2 * og) * 3 + 2] += p2 * f0;
                kvm[(2 * og + 1) * 3 + 0] += p0 * f1; kvm[(2 * og + 1) * 3 + 1] += p1 * f1; kvm[(2 * og + 1) * 3 + 2] += p2 * f1;
            }
        }
        {
            const float p0 = (a1 * sqm.w - a2 * sqm.z) * INV_SQRT2;
            const float p1 = (a2 * sqm.y - a0 * sqm.w) * INV_SQRT2;
            const float p2 = (a0 * sqm.z - a1 * sqm.y) * INV_SQRT2;
#pragma unroll
            for (int og = 0; og < 2; og++) {
                ull w0, w1;
                gch1(W + (144 + i * 2 + og) * 64, hhm, w0, w1);
                const float f0 = hsum2(w0), f1 = hsum2(w1);
                kvm[(2 * og) * 3 + 0] += p0 * f0; kvm[(2 * og) * 3 + 1] += p1 * f0; kvm[(2 * og) * 3 + 2] += p2 * f0;
                kvm[(2 * og + 1) * 3 + 0] += p0 * f1; kvm[(2 * og + 1) * 3 + 1] += p1 * f1; kvm[(2 * og + 1) * 3 + 2] += p2 * f1;
            }
        }
    }
}

// ================= K kernel =================
#define KK_SMEM ((512 + 10240) * 4)

__global__ __launch_bounds__(128, 4) void k_K(
    const float* __restrict__ node_ft, const void* __restrict__ ei,
    const float* __restrict__ edge_sh, const float* __restrict__ edge_scalars,
    const float* __restrict__ w1k, const float* __restrict__ w2k, int E) {
    extern __shared__ float sm[];
    const int tid = threadIdx.x;
    for (int i = tid * 4; i < 512; i += 512) *(float4*)(sm + i) = *(const float4*)(w1k + i);
    pack_w2<160, 320, 0>((float4*)(sm + 512), w2k, tid);
    __syncthreads();

    const int par = tid & 1;
    const int e0 = blockIdx.x * 128 + (tid >> 1) * 2;
    const int e1 = e0 + 1;
    const bool v0 = (e0 < E), v1 = (e1 < E);
    const int ec0 = v0 ? e0 : 0, ec1 = v1 ? e1 : 0;
    const ll snd0 = eidx(ei, ec0), snd1 = eidx(ei, ec1);
    const float4 sq0 = *(const float4*)(edge_sh + (size_t)ec0 * 4);
    const float4 sq1 = *(const float4*)(edge_sh + (size_t)ec1 * 4);

    ull hh0[8], hh1[8];
    {
        float es[16];
        load_es(es, edge_scalars, ec0); compute_h16p(sm, es, hh0, par);
        load_es(es, edge_scalars, ec1); compute_h16p(sm, es, hh1, par);
    }
    const float* W = sm + 512 + par * 4;
    const float* nf0 = node_ft + (size_t)snd0 * 40;
    const float* nf1 = node_ft + (size_t)snd1 * 40;

    float sS[8];
    // ---------- scalar pass: 2 sub-blocks of 4 outputs ----------
#pragma unroll
    for (int sub = 0; sub < 2; sub++) {
        ull aS[8];
#pragma unroll
        for (int o = 0; o < 8; o++) aS[o] = 0;
        // path1 (xs * shs), coefficients streamed in float4 chunks
#pragma unroll
        for (int t = 0; t < 4; t++) {
            const float4 x0 = *(const float4*)(nf0 + t * 4);
            const float4 x1 = *(const float4*)(nf1 + t * 4);
            const float xa0[4] = {x0.x, x0.y, x0.z, x0.w};
            const float xa1[4] = {x1.x, x1.y, x1.z, x1.w};
#pragma unroll
            for (int u = 0; u < 4; u++) {
                const int i = t * 4 + u;
                const float c0 = xa0[u] * sq0.x, c1 = xa1[u] * sq1.x;
                const ull cc0 = pack2(c0, c0), cc1 = pack2(c1, c1);
#pragma unroll
                for (int og = 0; og < 2; og++) {
                    ull w00, w10, w01, w11;
                    gch(W + (i * 4 + sub * 2 + og) * 64, hh0, hh1, w00, w10, w01, w11);
                    fma2(aS[(2 * og) * 2 + 0], w00, cc0); fma2(aS[(2 * og + 1) * 2 + 0], w10, cc0);
                    fma2(aS[(2 * og) * 2 + 1], w01, cc1); fma2(aS[(2 * og + 1) * 2 + 1], w11, cc1);
                }
            }
        }
        // path2
        {
            float c20[8], c21[8];
            compute_c2(nf0, sq0, c20);
            compute_c2(nf1, sq1, c21);
#pragma unroll
            for (int i = 0; i < 8; i++) {
                const ull cc0 = pack2(c20[i], c20[i]), cc1 = pack2(c21[i], c21[i]);
#pragma unroll
                for (int og = 0; og < 2; og++) {
                    ull w00, w10, w01, w11;
                    gch(W + (64 + i * 4 + sub * 2 + og) * 64, hh0, hh1, w00, w10, w01, w11);
                    fma2(aS[(2 * og) * 2 + 0], w00, cc0); fma2(aS[(2 * og + 1) * 2 + 0], w10, cc0);
                    fma2(aS[(2 * og) * 2 + 1], w01, cc1); fma2(aS[(2 * og + 1) * 2 + 1], w11, cc1);
                }
            }
        }
#pragma unroll
        for (int ol = 0; ol < 4; ol++) {
            const float u0 = comb(hsum2(aS[ol * 2 + 0]));
            const float u1 = comb(hsum2(aS[ol * 2 + 1]));
            sS[sub * 4 + ol] = par ? u1 : u0;
        }
    }

    // ---------- vector pass ----------
    float kv0[12], kv1[12];
    {
        ull t3[8];
#pragma unroll
        for (int o = 0; o < 8; o++) t3[o] = 0;
#pragma unroll
        for (int t = 0; t < 4; t++) {
            const float4 x0 = *(const float4*)(nf0 + t * 4);
            const float4 x1 = *(const float4*)(nf1 + t * 4);
            const float xa0[4] = {x0.x, x0.y, x0.z, x0.w};
            const float xa1[4] = {x1.x, x1.y, x1.z, x1.w};
#pragma unroll
            for (int u = 0; u < 4; u++) {
                const int i = t * 4 + u;
                const ull xx0 = pack2(xa0[u], xa0[u]), xx1 = pack2(xa1[u], xa1[u]);
#pragma unroll
                for (int og = 0; og < 2; og++) {
                    ull w00, w10, w01, w11;
                    gch(W + (96 + i * 2 + og) * 64, hh0, hh1, w00, w10, w01, w11);
                    fma2(t3[(2 * og) * 2 + 0], w00, xx0); fma2(t3[(2 * og + 1) * 2 + 0], w10, xx0);
                    fma2(t3[(2 * og) * 2 + 1], w01, xx1); fma2(t3[(2 * og + 1) * 2 + 1], w11, xx1);
                }
            }
        }
#pragma unroll
        for (int o = 0; o < 4; o++) {
            const float t0 = hsum2(t3[o * 2 + 0]), t1 = hsum2(t3[o * 2 + 1]);
            kv0[o * 3 + 0] = t0 * sq0.y; kv0[o * 3 + 1] = t0 * sq0.z; kv0[o * 3 + 2] = t0 * sq0.w;
            kv1[o * 3 + 0] = t1 * sq1.y; kv1[o * 3 + 1] = t1 * sq1.z; kv1[o * 3 + 2] = t1 * sq1.w;
        }
    }
    // paths 4 & 5, one edge at a time (keeps xv live range small)
    k45(W, nf0, sq0, hh0, kv0);
    k45(W, nf1, sq1, hh1, kv1);

    float sV[12];
#pragma unroll
    for (int o = 0; o < 12; o++) {
        const float u0 = comb(kv0[o]);
        const float u1 = comb(kv1[o]);
        sV[o] = par ? u1 : u0;
    }

    const int eMy = par ? ec1 : ec0;
    const bool vMy = par ? v1 : v0;
    if (vMy) {
        const ll rcv = eidx(ei, E + eMy);
        const float* qt = g_qt + (size_t)rcv * 20;
        float dS = 0.f, dV = 0.f;
#pragma unroll
        for (int o = 0; o < 8; o++) dS += __ldg(qt + o) * sS[o];
#pragma unroll
        for (int o = 0; o < 12; o++) dV += __ldg(qt + 8 + o) * sV[o];
        const float dot = (dS * INV_SQRT24 + dV * (INV_SQRT32 * INV_SQRT3)) * INV_SQRT80;
        const float exv = __expf(dot);
        g_ex[eMy] = exv;
        atomicAdd(&g_z[rcv], exv);
    }
}

// ================= Vs kernel: 16 scalar outputs, 4 sub-blocks =================
#define VS_SMEM ((512 + 12288) * 4)

__global__ __launch_bounds__(128, 4) void k_Vs(
    const float* __restrict__ node_ft, const void* __restrict__ ei,
    const float* __restrict__ edge_sh, const float* __restrict__ edge_scalars,
    const float* __restrict__ w1v, const float* __restrict__ w2v, int E) {
    extern __shared__ float sm[];
    const int tid = threadIdx.x;
    for (int i = tid * 4; i < 512; i += 512) *(float4*)(sm + i) = *(const float4*)(w1v + i);
    pack_w2<192, 640, 0>((float4*)(sm + 512), w2v, tid);
    __syncthreads();

    const int par = tid & 1;
    const int e0 = blockIdx.x * 128 + (tid >> 1) * 2;
    const int e1 = e0 + 1;
    const bool v0 = (e0 < E), v1 = (e1 < E);
    const int ec0 = v0 ? e0 : 0, ec1 = v1 ? e1 : 0;
    const ll snd0 = eidx(ei, ec0), snd1 = eidx(ei, ec1);
    const float4 sq0 = *(const float4*)(edge_sh + (size_t)ec0 * 4);
    const float4 sq1 = *(const float4*)(edge_sh + (size_t)ec1 * 4);

    ull hh0[8], hh1[8];
    {
        float es[16];
        load_es(es, edge_scalars, ec0); compute_h16p(sm, es, hh0, par);
        load_es(es, edge_scalars, ec1); compute_h16p(sm, es, hh1, par);
    }
    const float* W = sm + 512 + par * 4;
    const float* nf0 = node_ft + (size_t)snd0 * 40;
    const float* nf1 = node_ft + (size_t)snd1 * 40;

    const int eMy = par ? ec1 : ec0;
    const bool vMy = par ? v1 : v0;

#pragma unroll
    for (int sub = 0; sub < 4; sub++) {
        ull aS[8];
#pragma unroll
        for (int o = 0; o < 8; o++) aS[o] = 0;
        // path1
#pragma unroll
        for (int t = 0; t < 4; t++) {
            const float4 x0 = *(const float4*)(nf0 + t * 4);
            const float4 x1 = *(const float4*)(nf1 + t * 4);
            const float xa0[4] = {x0.x, x0.y, x0.z, x0.w};
            const float xa1[4] = {x1.x, x1.y, x1.z, x1.w};
#pragma unroll
            for (int u = 0; u < 4; u++) {
                const int i = t * 4 + u;
                const float c0 = xa0[u] * sq0.x, c1 = xa1[u] * sq1.x;
                const ull cc0 = pack2(c0, c0), cc1 = pack2(c1, c1);
#pragma unroll
                for (int og = 0; og < 2; og++) {
                    ull w00, w10, w01, w11;
                    gch(W + (i * 8 + sub * 2 + og) * 64, hh0, hh1, w00, w10, w01, w11);
                    fma2(aS[(2 * og) * 2 + 0], w00, cc0); fma2(aS[(2 * og + 1) * 2 + 0], w10, cc0);
                    fma2(aS[(2 * og) * 2 + 1], w01, cc1); fma2(aS[(2 * og + 1) * 2 + 1], w11, cc1);
                }
            }
        }
        // path2
        {
            float c20[8], c21[8];
            compute_c2(nf0, sq0, c20);
            compute_c2(nf1, sq1, c21);
#pragma unroll
            for (int i = 0; i < 8; i++) {
                const ull cc0 = pack2(c20[i], c20[i]), cc1 = pack2(c21[i], c21[i]);
#pragma unroll
                for (int og = 0; og < 2; og++) {
                    ull w00, w10, w01, w11;
                    gch(W + (128 + i * 8 + sub * 2 + og) * 64, hh0, hh1, w00, w10, w01, w11);
                    fma2(aS[(2 * og) * 2 + 0], w00, cc0); fma2(aS[(2 * og + 1) * 2 + 0], w10, cc0);
                    fma2(aS[(2 * og) * 2 + 1], w01, cc1); fma2(aS[(2 * og + 1) * 2 + 1], w11, cc1);
                }
            }
        }
        float s[4];
#pragma unroll
        for (int ol = 0; ol < 4; ol++) {
            const float u0 = comb(hsum2(aS[ol * 2 + 0]));
            const float u1 = comb(hsum2(aS[ol * 2 + 1]));
            s[ol] = (par ? u1 : u0) * INV_SQRT24;
        }
        if (vMy)
            *(float4*)(g_vv + (size_t)eMy * 40 + sub * 4) = make_float4(s[0], s[1], s[2], s[3]);
    }
}

// Vv paths 4+5 for one edge, one sub-block (4 outputs)
__device__ __forceinline__ void v45(const float* __restrict__ W, const float* __restrict__ nfm,
                                    const float4 sqm, const ull* hhm, float* vvm, int sub) {
    float xv[24];
    const float4* q = (const float4*)(nfm + 16);
#pragma unroll
    for (int t = 0; t < 6; t++) {
        float4 v = q[t];
        xv[t * 4 + 0] = v.x; xv[t * 4 + 1] = v.y; xv[t * 4 + 2] = v.z; xv[t * 4 + 3] = v.w;
    }
#pragma unroll
    for (int i = 0; i < 8; i++) {
        const float a0 = xv[i * 3], a1 = xv[i * 3 + 1], a2 = xv[i * 3 + 2];
        {
            const float p0 = a0 * sqm.x, p1 = a1 * sqm.x, p2 = a2 * sqm.x;
#pragma unroll
            for (int og = 0; og < 2; og++) {
                ull w0, w1;
                gch1(W + (64 + i * 4 + sub * 2 + og) * 64, hhm, w0, w1);
                const float f0 = hsum2(w0), f1 = hsum2(w1);
                vvm[(2 * og) * 3 + 0] += p0 * f0; vvm[(2 * og) * 3 + 1] += p1 * f0; vvm[(2 * og) * 3 + 2] += p2 * f0;
                vvm[(2 * og + 1) * 3 + 0] += p0 * f1; vvm[(2 * og + 1) * 3 + 1] += p1 * f1; vvm[(2 * og + 1) * 3 + 2] += p2 * f1;
            }
        }
        {
            const float p0 = (a1 * sqm.w - a2 * sqm.z) * INV_SQRT2;
            const float p1 = (a2 * sqm.y - a0 * sqm.w) * INV_SQRT2;
            const float p2 = (a0 * sqm.z - a1 * sqm.y) * INV_SQRT2;
#pragma unroll
            for (int og = 0; og < 2; og++) {
                ull w0, w1;
                gch1(W + (96 + i * 4 + sub * 2 + og) * 64, hhm, w0, w1);
                const float f0 = hsum2(w0), f1 = hsum2(w1);
                vvm[(2 * og) * 3 + 0] += p0 * f0; vvm[(2 * og) * 3 + 1] += p1 * f0; vvm[(2 * og) * 3 + 2] += p2 * f0;
                vvm[(2 * og + 1) * 3 + 0] += p0 * f1; vvm[(2 * og + 1) * 3 + 1] += p1 * f1; vvm[(2 * og + 1) * 3 + 2] += p2 * f1;
            }
        }
    }
}

// ================= Vv kernel: 8 vector outputs, 2 sub-blocks =================
#define VV_SMEM ((512 + 8192) * 4)

__global__ __launch_bounds__(128, 4) void k_Vv(
    const float* __restrict__ node_ft, const void* __restrict__ ei,
    const float* __restrict__ edge_sh, const float* __restrict__ edge_scalars,
    const float* __restrict__ w1v, const float* __restrict__ w2v, int E) {
    extern __shared__ float sm[];
    const int tid = threadIdx.x;
    for (int i = tid * 4; i < 512; i += 512) *(float4*)(sm + i) = *(const float4*)(w1v + i);
    pack_w2<128, 640, 384>((float4*)(sm + 512), w2v, tid);
    __syncthreads();

    const int par = tid & 1;
    const int e0 = blockIdx.x * 128 + (tid >> 1) * 2;
    const int e1 = e0 + 1;
    const bool v0 = (e0 < E), v1 = (e1 < E);
    const int ec0 = v0 ? e0 : 0, ec1 = v1 ? e1 : 0;
    const ll snd0 = eidx(ei, ec0), snd1 = eidx(ei, ec1);
    const float4 sq0 = *(const float4*)(edge_sh + (size_t)ec0 * 4);
    const float4 sq1 = *(const float4*)(edge_sh + (size_t)ec1 * 4);

    ull hh0[8], hh1[8];
    {
        float es[16];
        load_es(es, edge_scalars, ec0); compute_h16p(sm, es, hh0, par);
        load_es(es, edge_scalars, ec1); compute_h16p(sm, es, hh1, par);
    }
    const float* W = sm + 512 + par * 4;
    const float* nf0 = node_ft + (size_t)snd0 * 40;
    const float* nf1 = node_ft + (size_t)snd1 * 40;

    const int eMy = par ? ec1 : ec0;
    const bool vMy = par ? v1 : v0;

#pragma unroll
    for (int sub = 0; sub < 2; sub++) {
        float vv0[12], vv1[12];
        {   // path3 -> t3 for this sub-block's 4 outputs
            ull t3[8];
#pragma unroll
            for (int o = 0; o < 8; o++) t3[o] = 0;
#pragma unroll
            for (int t = 0; t < 4; t++) {
                const float4 x0 = *(const float4*)(nf0 + t * 4);
                const float4 x1 = *(const float4*)(nf1 + t * 4);
                const float xa0[4] = {x0.x, x0.y, x0.z, x0.w};
                const float xa1[4] = {x1.x, x1.y, x1.z, x1.w};
#pragma unroll
                for (int u = 0; u < 4; u++) {
                    const int i = t * 4 + u;
                    const ull xx0 = pack2(xa0[u], xa0[u]), xx1 = pack2(xa1[u], xa1[u]);
#pragma unroll
                    for (int og = 0; og < 2; og++) {
                        ull w00, w10, w01, w11;
                        gch(W + (i * 4 + sub * 2 + og) * 64, hh0, hh1, w00, w10, w01, w11);
                        fma2(t3[(2 * og) * 2 + 0], w00, xx0); fma2(t3[(2 * og + 1) * 2 + 0], w10, xx0);
                        fma2(t3[(2 * og) * 2 + 1], w01, xx1); fma2(t3[(2 * og + 1) * 2 + 1], w11, xx1);
                    }
                }
            }
#pragma unroll
            for (int o = 0; o < 4; o++) {
                const float t0 = hsum2(t3[o * 2 + 0]), t1 = hsum2(t3[o * 2 + 1]);
                vv0[o * 3 + 0] = t0 * sq0.y; vv0[o * 3 + 1] = t0 * sq0.z; vv0[o * 3 + 2] = t0 * sq0.w;
                vv1[o * 3 + 0] = t1 * sq1.y; vv1[o * 3 + 1] = t1 * sq1.z; vv1[o * 3 + 2] = t1 * sq1.w;
            }
        }
        v45(W, nf0, sq0, hh0, vv0, sub);
        v45(W, nf1, sq1, hh1, vv1, sub);

        float s[12];
#pragma unroll
        for (int o = 0; o < 12; o++) {
            const float u0 = comb(vv0[o]);
            const float u1 = comb(vv1[o]);
            s[o] = (par ? u1 : u0) * INV_SQRT32;
        }
        if (vMy) {
            float* dst = g_vv + (size_t)eMy * 40 + 16 + sub * 12;
#pragma unroll
            for (int t = 0; t < 3; t++)
                *(float4*)(dst + t * 4) = make_float4(s[t * 4 + 0], s[t * 4 + 1], s[t * 4 + 2], s[t * 4 + 3]);
        }
    }
}

// ---------------- scatter: softmax normalize + vector reduction ----------------
__global__ void k_scatter(const void* __restrict__ ei, float* __restrict__ out, int E) {
    int e = blockIdx.x * blockDim.x + threadIdx.x;
    if (e >= E) return;
    const ll r = eidx(ei, E + e);
    const float a = sqrtf(g_ex[e] / g_z[r]);
    const float4* v = (const float4*)(g_vv + (size_t)e * 40);
    float* o = out + (size_t)r * 40;
#pragma unroll
    for (int t = 0; t < 10; t++) {
        float4 w = v[t];
        asm volatile("red.global.add.v4.f32 [%0], {%1, %2, %3, %4};"
                     :: "l"(o + t * 4), "f"(a * w.x), "f"(a * w.y), "f"(a * w.z), "f"(a * w.w)
                     : "memory");
    }
}

extern "C" void kernel_launch(void* const* d_in, const int* in_sizes, int n_in,
                              void* d_out, int out_size) {
    const float* node_ft      = (const float*)d_in[0];
    const void*  ei           = d_in[1];
    const float* edge_sh      = (const float*)d_in[2];
    const float* edge_scalars = (const float*)d_in[3];
    const float* wqs          = (const float*)d_in[4];
    const float* wqv          = (const float*)d_in[5];
    const float* fckw1        = (const float*)d_in[6];
    const float* fckw2        = (const float*)d_in[7];
    const float* fcvw1        = (const float*)d_in[8];
    const float* fcvw2        = (const float*)d_in[9];
    const float* wds          = (const float*)d_in[10];
    const float* wdv          = (const float*)d_in[11];
    float* out = (float*)d_out;

    const int N = in_sizes[0] / 40;
    const int E = in_sizes[1] / 2;
    const int gE = (E + 127) / 128;

    cudaFuncSetAttribute(k_K,  cudaFuncAttributeMaxDynamicSharedMemorySize, KK_SMEM);
    cudaFuncSetAttribute(k_Vs, cudaFuncAttributeMaxDynamicSharedMemorySize, VS_SMEM);
    cudaFuncSetAttribute(k_Vv, cudaFuncAttributeMaxDynamicSharedMemorySize, VV_SMEM);

    k_detect<<<1, 256>>>((const int*)ei, 2 * E);
    k_zero<<<(N * 40 + 255) / 256, 256>>>(out, N);
    k_query<<<(N + 255) / 256, 256>>>(node_ft, wqs, wqv, wds, wdv, N);
    k_K<<<gE, 128, KK_SMEM>>>(node_ft, ei, edge_sh, edge_scalars, fckw1, fckw2, E);
    k_Vs<<<gE, 128, VS_SMEM>>>(node_ft, ei, edge_sh, edge_scalars, fcvw1, fcvw2, E);
    k_Vv<<<gE, 128, VV_SMEM>>>(node_ft, ei, edge_sh, edge_scalars, fcvw1, fcvw2, E);
    k_scatter<<<(E + 255) / 256, 256>>>(ei, out, E);
}